// round 8
// baseline (speedup 1.0000x reference)
#include <cuda_runtime.h>
#include <cstdint>

#define BB 64
#define RR 32
#define NN 16384
#define DD 64
#define OO 8
#define CHUNKS 8
#define NC (NN / CHUNKS)   // 2048 elements per chunk-block

// Scratch: zero at entry of every launch (.bss first call; last block per b
// self-cleans each call). No fences anywhere — ordering via ATOMG completion.
__device__ float g_s[BB * DD];
__device__ float g_cnt[BB];
__device__ int   g_arrive[BB];

__global__ void __launch_bounds__(256) fused_kernel(
    const float* __restrict__ h_context,
    const float* __restrict__ l_local,
    const float* __restrict__ lambda_so,
    const int* __restrict__ center_o,
    const int* __restrict__ o_types,
    const unsigned int* __restrict__ adj,   // bool as 32-bit word (i32/f32 0|1)
    const unsigned int* __restrict__ two,
    float* __restrict__ out)
{
    __shared__ int   s_idx[NC];
    __shared__ int   s_count;
    __shared__ float s_acc[DD];
    __shared__ int   s_last;
    volatile __shared__ float s_sink[8];   // ATOMG-return sink (forces completion)

    const int b    = blockIdx.x / CHUNKS;
    const int c    = blockIdx.x % CHUNKS;
    const int tid  = threadIdx.x;
    const int w    = tid >> 5;
    const int lane = tid & 31;

    if (tid == 0) s_count = 0;
    if (tid < DD) s_acc[tid] = 0.0f;

    const int co = __ldg(&center_o[b]);

    // Prefetch finalize inputs (used only if this block arrives last; reads
    // are L2-hits for 7 of 8 sibling blocks). Thread (w,lane) owns float2
    // col-pair 2*lane of rows w, w+8, w+16, w+24.
    const float2* ll2 = reinterpret_cast<const float2*>(l_local + (size_t)b * RR * DD);
    float2 ll[4];
    float  lam[4];
    #pragma unroll
    for (int rr = 0; rr < 4; rr++) {
        ll[rr]  = __ldg(ll2 + (size_t)(w + rr * 8) * (DD / 2) + lane);
        lam[rr] = __ldg(&lambda_so[(w + rr * 8) * OO + co]);
    }

    const int base = b * NN + c * NC;
    const int4*  ot4 = reinterpret_cast<const int4*>(o_types + base);
    const uint4* a4  = reinterpret_cast<const uint4*>(adj + base);
    const uint4* t4  = reinterpret_cast<const uint4*>(two + base);

    // ---- Phase A: front-batched loads (6 independent LDG.128), then compact
    int4  ot0 = ot4[tid],      ot1 = ot4[tid + 256];
    uint4 a0  = a4[tid],       a1  = a4[tid + 256];
    uint4 t0  = t4[tid],       t1  = t4[tid + 256];
    __syncthreads();   // s_count/s_acc init visible

    int n0 = c * NC + tid * 4;
    if (ot0.x == co && (a0.x | t0.x)) s_idx[atomicAdd(&s_count, 1)] = n0 + 0;
    if (ot0.y == co && (a0.y | t0.y)) s_idx[atomicAdd(&s_count, 1)] = n0 + 1;
    if (ot0.z == co && (a0.z | t0.z)) s_idx[atomicAdd(&s_count, 1)] = n0 + 2;
    if (ot0.w == co && (a0.w | t0.w)) s_idx[atomicAdd(&s_count, 1)] = n0 + 3;
    n0 = c * NC + (tid + 256) * 4;
    if (ot1.x == co && (a1.x | t1.x)) s_idx[atomicAdd(&s_count, 1)] = n0 + 0;
    if (ot1.y == co && (a1.y | t1.y)) s_idx[atomicAdd(&s_count, 1)] = n0 + 1;
    if (ot1.z == co && (a1.z | t1.z)) s_idx[atomicAdd(&s_count, 1)] = n0 + 2;
    if (ot1.w == co && (a1.w | t1.w)) s_idx[atomicAdd(&s_count, 1)] = n0 + 3;
    __syncthreads();

    const int cnt = s_count;   // ~15 expected

    // ---- Phase B: 8 warps cooperatively normalize+accumulate hits ----
    const float2* ctx2 = reinterpret_cast<const float2*>(h_context + (size_t)b * NN * DD);
    float accx = 0.0f, accy = 0.0f;
    for (int i = w; i < cnt; i += 8) {
        int n = s_idx[i];
        float2 x = __ldg(ctx2 + (size_t)n * (DD / 2) + lane);
        float sq = x.x * x.x + x.y * x.y;
        #pragma unroll
        for (int o = 16; o; o >>= 1)
            sq += __shfl_xor_sync(0xffffffffu, sq, o);
        float rinv = rsqrtf(fmaxf(sq, 1e-12f));
        accx += x.x * rinv;
        accy += x.y * rinv;
    }
    atomicAdd(&s_acc[2 * lane + 0], accx);
    atomicAdd(&s_acc[2 * lane + 1], accy);
    __syncthreads();

    // ---- Publish partials with completion-enforced ATOMG ----
    // Return value -> volatile STS sink; the next __syncthreads drains STS,
    // so every RMW is performed at L2 before the arrive atomic below.
    if (tid < DD) {
        float old = atomicAdd(&g_s[b * DD + tid], s_acc[tid]);
        s_sink[tid & 7] = old;
    }
    if (tid == DD) {
        float old = atomicAdd(&g_cnt[b], (float)cnt);
        s_sink[0] = old;
    }
    __syncthreads();

    if (tid == 0) {
        int prev = atomicAdd(&g_arrive[b], 1);
        s_last = (prev == CHUNKS - 1) ? 1 : 0;
    }
    __syncthreads();
    if (!s_last) return;

    // ---- Finalize (last-arriving block for this b) ----
    __shared__ float sv[DD];
    __shared__ float s_scnt;
    if (tid < DD) {
        float v = __ldcg(&g_s[b * DD + tid]);   // L2-direct read
        sv[tid] = v;
        g_s[b * DD + tid] = 0.0f;               // self-clean for next replay
    }
    if (tid == DD) {
        s_scnt = __ldcg(&g_cnt[b]);
        g_cnt[b] = 0.0f;
    }
    if (tid == 0) g_arrive[b] = 0;              // restore replay invariant
    __syncthreads();

    const float cval = s_scnt;
    #pragma unroll
    for (int rr = 0; rr < 4; rr++) {
        int r = w + rr * 8;
        float2 x = ll[rr];
        float sq = x.x * x.x + x.y * x.y;
        float dp = x.x * sv[2 * lane] + x.y * sv[2 * lane + 1];
        #pragma unroll
        for (int o = 16; o; o >>= 1) {
            sq += __shfl_xor_sync(0xffffffffu, sq, o);
            dp += __shfl_xor_sync(0xffffffffu, dp, o);
        }
        if (lane == 0) {
            float rinv = rsqrtf(fmaxf(sq, 1e-12f));
            float avg = dp * rinv / fmaxf(cval, 1e-9f);
            float wv = fmaxf(lam[rr] / fmaxf(cval, 1.0f), 0.0f) * (1.0f - avg);
            out[b * RR + r] = wv;
        }
    }
}

extern "C" void kernel_launch(void* const* d_in, const int* in_sizes, int n_in,
                              void* d_out, int out_size) {
    const float*        l_local   = (const float*)d_in[0];
    const float*        h_context = (const float*)d_in[1];
    const float*        lambda_so = (const float*)d_in[2];
    const int*          center_o  = (const int*)d_in[3];
    const int*          o_types   = (const int*)d_in[4];
    const unsigned int* adj       = (const unsigned int*)d_in[5];
    const unsigned int* two       = (const unsigned int*)d_in[6];
    float*              out       = (float*)d_out;

    fused_kernel<<<BB * CHUNKS, 256>>>(h_context, l_local, lambda_so,
                                       center_o, o_types, adj, two, out);
}

// round 12
// speedup vs baseline: 1.6196x; 1.6196x over previous
#include <cuda_runtime.h>
#include <cstdint>

#define BB 64
#define RR 32
#define NN 16384
#define DD 64
#define OO 8
#define TPB 1024
#define NWARP 32
#define CAP 2048               // hit-list capacity (expected ~121/block)

// One block per b, 1024 threads. Phase A: branchless streaming scan ->
// per-thread 16-bit hit mask (max MLP, no ballots). Phase A2: tiny shared-
// atomic compaction (~121 hits). Phase B: warps gather rows with batched
// preloads. Phase C: epilogue (warp w == output row r).
__global__ void __launch_bounds__(TPB, 1) fused_kernel(
    const float* __restrict__ h_context,
    const float* __restrict__ l_local,
    const float* __restrict__ lambda_so,
    const int* __restrict__ center_o,
    const int* __restrict__ o_types,
    const unsigned int* __restrict__ adj,   // bool as 32-bit word (i32/f32 0|1)
    const unsigned int* __restrict__ two,
    float* __restrict__ out)
{
    __shared__ int   s_idx[CAP];
    __shared__ int   s_count;
    __shared__ float s_acc[DD];

    const int b    = blockIdx.x;
    const int tid  = threadIdx.x;
    const int w    = tid >> 5;     // warp id == output row r
    const int lane = tid & 31;

    // Epilogue operands resident from the start: thread tid's float2 of
    // l_local[b] is row (tid/32)=w, cols {2*lane, 2*lane+1}.
    const float2 ll = reinterpret_cast<const float2*>(
        l_local + (size_t)b * RR * DD)[tid];
    const int   co  = __ldg(&center_o[b]);
    const float lam = __ldg(&lambda_so[w * OO + co]);

    if (tid == 0) s_count = 0;
    if (tid < DD) s_acc[tid] = 0.0f;

    // ---- Phase A: streaming scan, private hit mask (no cross-lane ops) ----
    // uint4 index u = g*1024 + tid, g in 0..3; covers elements
    // g*4096 + tid*4 + j  (j = 0..3). Hit-mask bit = g*4 + j.
    const int4*  ot4 = reinterpret_cast<const int4*>(o_types + b * NN);
    const uint4* a4  = reinterpret_cast<const uint4*>(adj     + b * NN);
    const uint4* t4  = reinterpret_cast<const uint4*>(two     + b * NN);

    unsigned hm = 0;
    #pragma unroll
    for (int half = 0; half < 2; half++) {
        const int uA = (2 * half + 0) * 1024 + tid;
        const int uB = (2 * half + 1) * 1024 + tid;
        // 6 independent LDG.128 back-to-back
        int4  otA = ot4[uA];  int4  otB = ot4[uB];
        uint4 aA  = a4[uA];   uint4 aB  = a4[uB];
        uint4 tA  = t4[uA];   uint4 tB  = t4[uB];

        unsigned gA = (2 * half + 0) * 4, gB = (2 * half + 1) * 4;
        hm |= (unsigned)((otA.x == co) && (aA.x | tA.x)) << (gA + 0);
        hm |= (unsigned)((otA.y == co) && (aA.y | tA.y)) << (gA + 1);
        hm |= (unsigned)((otA.z == co) && (aA.z | tA.z)) << (gA + 2);
        hm |= (unsigned)((otA.w == co) && (aA.w | tA.w)) << (gA + 3);
        hm |= (unsigned)((otB.x == co) && (aB.x | tB.x)) << (gB + 0);
        hm |= (unsigned)((otB.y == co) && (aB.y | tB.y)) << (gB + 1);
        hm |= (unsigned)((otB.z == co) && (aB.z | tB.z)) << (gB + 2);
        hm |= (unsigned)((otB.w == co) && (aB.w | tB.w)) << (gB + 3);
    }
    __syncthreads();   // s_count / s_acc init visible

    // ---- Phase A2: compaction (only ~121 threads/block enter) ----
    if (hm) {
        int base = atomicAdd(&s_count, __popc(hm));
        unsigned m = hm;
        while (m) {
            int k = __ffs(m) - 1; m &= m - 1;
            int n = (k >> 2) * 4096 + tid * 4 + (k & 3);
            if (base < CAP) s_idx[base] = n;
            base++;
        }
    }
    __syncthreads();

    const int cnt  = s_count;
    const int pcnt = (cnt < CAP) ? cnt : CAP;

    // ---- Phase B: warp-cooperative gather, 8-row preload batches ----
    const float2* ctx2 = reinterpret_cast<const float2*>(
        h_context + (size_t)b * NN * DD);
    float accx = 0.0f, accy = 0.0f;
    for (int bo = 0; bo < pcnt; bo += NWARP * 8) {
        float2 xs[8];
        #pragma unroll
        for (int k = 0; k < 8; k++) {
            int i = bo + k * NWARP + w;
            xs[k] = (i < pcnt)
                  ? __ldg(ctx2 + (size_t)s_idx[i] * (DD / 2) + lane)
                  : make_float2(0.0f, 0.0f);
        }
        #pragma unroll
        for (int k = 0; k < 8; k++) {
            float sq = xs[k].x * xs[k].x + xs[k].y * xs[k].y;
            #pragma unroll
            for (int o = 16; o; o >>= 1)
                sq += __shfl_xor_sync(0xffffffffu, sq, o);
            float rinv = rsqrtf(fmaxf(sq, 1e-12f));   // zero rows contribute 0
            accx += xs[k].x * rinv;
            accy += xs[k].y * rinv;
        }
    }
    atomicAdd(&s_acc[2 * lane + 0], accx);
    atomicAdd(&s_acc[2 * lane + 1], accy);
    __syncthreads();

    // ---- Phase C: epilogue (warp w == row r) ----
    const float cval = (float)cnt;
    float sq = ll.x * ll.x + ll.y * ll.y;
    float dp = ll.x * s_acc[2 * lane] + ll.y * s_acc[2 * lane + 1];
    #pragma unroll
    for (int o = 16; o; o >>= 1) {
        sq += __shfl_xor_sync(0xffffffffu, sq, o);
        dp += __shfl_xor_sync(0xffffffffu, dp, o);
    }
    if (lane == 0) {
        float rinv = rsqrtf(fmaxf(sq, 1e-12f));
        float avg = dp * rinv / fmaxf(cval, 1e-9f);
        float wv = fmaxf(lam / fmaxf(cval, 1.0f), 0.0f) * (1.0f - avg);
        out[b * RR + w] = wv;
    }
}

extern "C" void kernel_launch(void* const* d_in, const int* in_sizes, int n_in,
                              void* d_out, int out_size) {
    const float*        l_local   = (const float*)d_in[0];
    const float*        h_context = (const float*)d_in[1];
    const float*        lambda_so = (const float*)d_in[2];
    const int*          center_o  = (const int*)d_in[3];
    const int*          o_types   = (const int*)d_in[4];
    const unsigned int* adj       = (const unsigned int*)d_in[5];
    const unsigned int* two       = (const unsigned int*)d_in[6];
    float*              out       = (float*)d_out;

    fused_kernel<<<BB, TPB>>>(h_context, l_local, lambda_so,
                              center_o, o_types, adj, two, out);
}